// round 3
// baseline (speedup 1.0000x reference)
#include <cuda_runtime.h>
#include <cuda_bf16.h>
#include <math.h>

// ---------------- problem constants ----------------
#define T_TOK   4096
#define HID     4096
#define NH      32
#define NKV     8
#define HD      128
#define INTER   14336
#define BATCH   4
#define SEQ     1024
#define QKV_N   6144            // (NH + 2*NKV) * HD
#define UP_N    28672           // 2 * INTER
#define LIMIT   20.0f
#define LN_EPS  1e-5f
#define ATTN_SCALE 0.08838834764831845f  // 128^-0.5

// ---------------- device scratch (no allocations allowed) ----------------
__device__ float g_h[(size_t)T_TOK * HID];        // h = hidden + residual
__device__ float g_norm[(size_t)T_TOK * HID];     // ln1 / ln2 output (reused)
__device__ float g_qkv[(size_t)T_TOK * QKV_N];    // qkv projections (rope in-place)
__device__ float g_ctx[(size_t)T_TOK * HID];      // attention context
__device__ float g_act[(size_t)T_TOK * INTER];    // gegelu(up) activations

// ---------------- LayerNorm (optionally fused residual add) ----------------
// grid = T_TOK rows, block = 256. HID/256 == 16 elements per thread.
__global__ void ln_kernel(const float* __restrict__ x,
                          const float* __restrict__ res,
                          const float* __restrict__ w,
                          const float* __restrict__ b,
                          float* __restrict__ h_out,
                          float* __restrict__ n_out) {
    __shared__ float sred[256];
    const int row = blockIdx.x;
    const int tid = threadIdx.x;
    const size_t base = (size_t)row * HID;

    float vals[16];
    float s = 0.f, s2 = 0.f;
#pragma unroll
    for (int i = 0; i < 16; i++) {
        int c = i * 256 + tid;
        float v = x[base + c];
        if (res)   v += res[base + c];
        if (h_out) h_out[base + c] = v;
        vals[i] = v;
        s += v;
        s2 += v * v;
    }
    // reduce sum
    sred[tid] = s; __syncthreads();
    for (int off = 128; off > 0; off >>= 1) {
        if (tid < off) sred[tid] += sred[tid + off];
        __syncthreads();
    }
    float mean = sred[0] * (1.0f / HID);
    __syncthreads();
    // reduce sumsq
    sred[tid] = s2; __syncthreads();
    for (int off = 128; off > 0; off >>= 1) {
        if (tid < off) sred[tid] += sred[tid + off];
        __syncthreads();
    }
    float var = sred[0] * (1.0f / HID) - mean * mean;
    float rstd = rsqrtf(var + LN_EPS);

#pragma unroll
    for (int i = 0; i < 16; i++) {
        int c = i * 256 + tid;
        n_out[base + c] = (vals[i] - mean) * rstd * w[c] + b[c];
    }
}

// ---------------- RoPE (in-place on q and k parts of qkv) ----------------
// grid = T_TOK, block = 256. (NH+NKV)*64 = 2560 rotation pairs per token.
__global__ void rope_kernel(float* __restrict__ qkv,
                            const float* __restrict__ cosp,
                            const float* __restrict__ sinp) {
    const int t = blockIdx.x;
    const float* cr = cosp + (size_t)t * 64;
    const float* sr = sinp + (size_t)t * 64;
    for (int i = threadIdx.x; i < (NH + NKV) * 64; i += 256) {
        int h = i >> 6;
        int d = i & 63;
        size_t base = (size_t)t * QKV_N +
                      (h < NH ? (size_t)h * HD : (size_t)NH * HD + (size_t)(h - NH) * HD);
        float c = cr[d], s = sr[d];
        float x1 = qkv[base + d];
        float x2 = qkv[base + 64 + d];
        qkv[base + d]      = x1 * c - x2 * s;
        qkv[base + 64 + d] = x2 * c + x1 * s;
    }
}

// ---------------- Flash attention (causal, GQA 4:1) ----------------
// grid = (SEQ/8, NH, BATCH), block = 256 (8 warps, 1 warp per query row).
__global__ void __launch_bounds__(256) attn_kernel(const float* __restrict__ qkv,
                                                   float* __restrict__ ctx) {
    __shared__ float Qs[8][132];
    __shared__ float Ks[32][132];
    __shared__ float Vs[32][132];

    const int qt = blockIdx.x;           // query tile of 8 rows
    const int h  = blockIdx.y;
    const int b  = blockIdx.z;
    const int tid  = threadIdx.x;
    const int warp = tid >> 5;
    const int lane = tid & 31;

    const int kvh  = h >> 2;             // NH/NKV = 4
    const int koff = NH * HD + kvh * HD;         // 4096 + kvh*128
    const int voff = NH * HD + NKV * HD + kvh * HD;

    // load 8 query rows into smem
    {
        int r = tid >> 5, c = (tid & 31) * 4;
        const float* src = qkv + (size_t)(b * SEQ + qt * 8 + r) * QKV_N + h * HD + c;
        *(float4*)&Qs[r][c] = *(const float4*)src;
    }

    const int qpos = qt * 8 + warp;      // local (within-batch) query position
    float m = -1e30f, l = 0.f;
    float ax = 0.f, ay = 0.f, az = 0.f, aw = 0.f;

    const int ntiles = (qt * 8 + 7) / 32 + 1;
    for (int kt = 0; kt < ntiles; kt++) {
        __syncthreads();
        // stage K and V tiles (32 keys x 128 dims)
#pragma unroll
        for (int i = 0; i < 4; i++) {
            int ch = i * 256 + tid;
            int r = ch >> 5, c = (ch & 31) * 4;
            size_t tk = (size_t)(b * SEQ + kt * 32 + r) * QKV_N;
            *(float4*)&Ks[r][c] = *(const float4*)&qkv[tk + koff + c];
            *(float4*)&Vs[r][c] = *(const float4*)&qkv[tk + voff + c];
        }
        __syncthreads();

        // score for key = lane
        float s = 0.f;
#pragma unroll
        for (int d4 = 0; d4 < 32; d4++) {
            float4 qv = *(const float4*)&Qs[warp][d4 * 4];
            float4 kv = *(const float4*)&Ks[lane][d4 * 4];
            s += qv.x * kv.x + qv.y * kv.y + qv.z * kv.z + qv.w * kv.w;
        }
        s *= ATTN_SCALE;
        int kpos = kt * 32 + lane;
        if (kpos > qpos) s = -1e30f;

        // warp max
        float tmax = s;
#pragma unroll
        for (int off = 16; off > 0; off >>= 1)
            tmax = fmaxf(tmax, __shfl_xor_sync(0xffffffffu, tmax, off));
        float mnew  = fmaxf(m, tmax);
        float scale = __expf(m - mnew);
        float p     = __expf(s - mnew);
        float psum = p;
#pragma unroll
        for (int off = 16; off > 0; off >>= 1)
            psum += __shfl_xor_sync(0xffffffffu, psum, off);
        l = l * scale + psum;
        ax *= scale; ay *= scale; az *= scale; aw *= scale;

#pragma unroll
        for (int j = 0; j < 32; j++) {
            float pj = __shfl_sync(0xffffffffu, p, j);
            float4 v = *(const float4*)&Vs[j][lane * 4];
            ax += pj * v.x; ay += pj * v.y; az += pj * v.z; aw += pj * v.w;
        }
        m = mnew;
    }

    float inv = 1.0f / l;
    size_t ob = (size_t)(b * SEQ + qpos) * HID + h * HD + lane * 4;
    float4 o = make_float4(ax * inv, ay * inv, az * inv, aw * inv);
    *(float4*)&ctx[ob] = o;
}

// ---------------- tiled fp32 SGEMM: C = A(MxK) @ B(KxN) ----------------
// 128x128 block tile, BK=8, 256 threads, 8x8 per-thread microtile.
// EPI 0: + bias (bias may be null)
// EPI 1: + addsrc (residual)
// EPI 2: + bias then gegelu pairs -> C has N/2 columns
__device__ __forceinline__ float gegelu_pair(float a_in, float lin_in) {
    float a   = fminf(a_in, LIMIT);
    float lin = fminf(fmaxf(lin_in, -LIMIT), LIMIT);
    float sig = 1.0f / (1.0f + __expf(-1.702f * a));
    return a * sig * (lin + 1.0f);
}

template <int EPI>
__global__ void __launch_bounds__(256) sgemm_k(const float* __restrict__ A,
                                               const float* __restrict__ Bm,
                                               const float* __restrict__ bias,
                                               const float* __restrict__ addsrc,
                                               float* __restrict__ C,
                                               int M, int N, int K) {
    __shared__ float As[8][128];
    __shared__ float Bs[8][128];

    const int tid = threadIdx.x;
    const int tx = tid & 15, ty = tid >> 4;
    const int bm = blockIdx.y, bn = blockIdx.x;

    const float* Ab = A + (size_t)bm * 128 * K;
    const float* Bb = Bm + (size_t)bn * 128;

    float acc[8][8];
#pragma unroll
    for (int i = 0; i < 8; i++)
#pragma unroll
        for (int j = 0; j < 8; j++) acc[i][j] = 0.f;

    const int ar = tid >> 1, ac = (tid & 1) * 4;     // A tile: 128 rows x 8 k
    const int brr = tid >> 5, bcc = (tid & 31) * 4;  // B tile: 8 k x 128 cols

    const int KT = K >> 3;
#pragma unroll 1
    for (int kt = 0; kt < KT; kt++) {
        float4 av = *(const float4*)&Ab[(size_t)ar * K + kt * 8 + ac];
        As[ac + 0][ar] = av.x;
        As[ac + 1][ar] = av.y;
        As[ac + 2][ar] = av.z;
        As[ac + 3][ar] = av.w;
        *(float4*)&Bs[brr][bcc] =
            *(const float4*)&Bb[(size_t)(kt * 8 + brr) * N + bcc];
        __syncthreads();

#pragma unroll
        for (int kk = 0; kk < 8; kk++) {
            float4 a0 = *(const float4*)&As[kk][ty * 4];
            float4 a1 = *(const float4*)&As[kk][ty * 4 + 64];
            float4 b0 = *(const float4*)&Bs[kk][tx * 4];
            float4 b1 = *(const float4*)&Bs[kk][tx * 4 + 64];
            float ra[8] = {a0.x, a0.y, a0.z, a0.w, a1.x, a1.y, a1.z, a1.w};
            float rb[8] = {b0.x, b0.y, b0.z, b0.w, b1.x, b1.y, b1.z, b1.w};
#pragma unroll
            for (int i = 0; i < 8; i++)
#pragma unroll
                for (int j = 0; j < 8; j++) acc[i][j] += ra[i] * rb[j];
        }
        __syncthreads();
    }

    // epilogue
#pragma unroll
    for (int i = 0; i < 8; i++) {
        int r = bm * 128 + ((i < 4) ? (ty * 4 + i) : (64 + ty * 4 + i - 4));
#pragma unroll
        for (int half = 0; half < 2; half++) {
            int c0 = bn * 128 + tx * 4 + half * 64;
            float v0 = acc[i][half * 4 + 0];
            float v1 = acc[i][half * 4 + 1];
            float v2 = acc[i][half * 4 + 2];
            float v3 = acc[i][half * 4 + 3];
            if (EPI == 2) {
                v0 += bias[c0 + 0]; v1 += bias[c0 + 1];
                v2 += bias[c0 + 2]; v3 += bias[c0 + 3];
                float2 o;
                o.x = gegelu_pair(v0, v1);
                o.y = gegelu_pair(v2, v3);
                *(float2*)&C[(size_t)r * (N >> 1) + (c0 >> 1)] = o;
            } else {
                if (EPI == 0 && bias) {
                    v0 += bias[c0 + 0]; v1 += bias[c0 + 1];
                    v2 += bias[c0 + 2]; v3 += bias[c0 + 3];
                }
                if (EPI == 1) {
                    float4 adv = *(const float4*)&addsrc[(size_t)r * N + c0];
                    v0 += adv.x; v1 += adv.y; v2 += adv.z; v3 += adv.w;
                }
                float4 o = make_float4(v0, v1, v2, v3);
                *(float4*)&C[(size_t)r * N + c0] = o;
            }
        }
    }
}

// ---------------- launcher ----------------
extern "C" void kernel_launch(void* const* d_in, const int* in_sizes, int n_in,
                              void* d_out, int out_size) {
    const float* hs     = (const float*)d_in[0];
    const float* res    = (const float*)d_in[1];
    const float* cosp   = (const float*)d_in[2];
    const float* sinp   = (const float*)d_in[3];
    /* d_in[4]: cu_seqlen_prefill (regular, unused) */
    const float* w_qkv  = (const float*)d_in[5];
    const float* b_qkv  = (const float*)d_in[6];
    const float* w_o    = (const float*)d_in[7];
    const float* w_ln1  = (const float*)d_in[8];
    const float* b_ln1  = (const float*)d_in[9];
    const float* w_ln2  = (const float*)d_in[10];
    const float* b_ln2  = (const float*)d_in[11];
    const float* w_up   = (const float*)d_in[12];
    const float* b_up   = (const float*)d_in[13];
    const float* w_down = (const float*)d_in[14];
    const float* b_down = (const float*)d_in[15];

    float* out     = (float*)d_out;
    float* mlp_out = out;                         // first output
    float* h2      = out + (size_t)T_TOK * HID;   // second output

    float *p_h, *p_norm, *p_qkv, *p_ctx, *p_act;
    cudaGetSymbolAddress((void**)&p_h,    g_h);
    cudaGetSymbolAddress((void**)&p_norm, g_norm);
    cudaGetSymbolAddress((void**)&p_qkv,  g_qkv);
    cudaGetSymbolAddress((void**)&p_ctx,  g_ctx);
    cudaGetSymbolAddress((void**)&p_act,  g_act);

    // 1) h = hs + res ; normed = LN1(h)
    ln_kernel<<<T_TOK, 256>>>(hs, res, w_ln1, b_ln1, p_h, p_norm);

    // 2) qkv = normed @ w_qkv + b_qkv
    sgemm_k<0><<<dim3(QKV_N / 128, T_TOK / 128), 256>>>(
        p_norm, w_qkv, b_qkv, nullptr, p_qkv, T_TOK, QKV_N, HID);

    // 3) RoPE in place on q,k
    rope_kernel<<<T_TOK, 256>>>(p_qkv, cosp, sinp);

    // 4) causal flash attention -> ctx
    attn_kernel<<<dim3(SEQ / 8, NH, BATCH), 256>>>(p_qkv, p_ctx);

    // 5) h2 = ctx @ w_o + h   (written to output)
    sgemm_k<1><<<dim3(HID / 128, T_TOK / 128), 256>>>(
        p_ctx, w_o, nullptr, p_h, h2, T_TOK, HID, HID);

    // 6) normed2 = LN2(h2)
    ln_kernel<<<T_TOK, 256>>>(h2, nullptr, w_ln2, b_ln2, nullptr, p_norm);

    // 7) act = gegelu(normed2 @ w_up + b_up)
    sgemm_k<2><<<dim3(UP_N / 128, T_TOK / 128), 256>>>(
        p_norm, w_up, b_up, nullptr, p_act, T_TOK, UP_N, HID);

    // 8) mlp_out = act @ w_down + b_down
    sgemm_k<0><<<dim3(HID / 128, T_TOK / 128), 256>>>(
        p_act, w_down, b_down, nullptr, mlp_out, T_TOK, HID, INTER);
}

// round 8
// speedup vs baseline: 2.6918x; 2.6918x over previous
#include <cuda_runtime.h>
#include <cuda_bf16.h>
#include <math.h>
#include <stdint.h>

// ---------------- problem constants ----------------
#define T_TOK   4096
#define HID     4096
#define NH      32
#define NKV     8
#define HD      128
#define INTER   14336
#define BATCH   4
#define SEQ     1024
#define QKV_N   6144            // (NH + 2*NKV) * HD
#define UP_N    28672           // 2 * INTER
#define LIMIT   20.0f
#define LN_EPS  1e-5f
#define ATTN_SCALE 0.08838834764831845f  // 128^-0.5

// tcgen05 only exists on arch-specific targets (sm_103a / sm_100a).
// The harness also compiles a generic compute_103 PTX pass, where these
// instructions are ILLEGAL -> guard them and provide an mma.sync fallback.
#if defined(__CUDA_ARCH_FEAT_SM103_ALL) || defined(__CUDA_ARCH_FEAT_SM100_ALL) || \
    defined(__CUDA_ARCH_FEAT_SM101_ALL)
#define USE_TCG 1
#else
#define USE_TCG 0
#endif

// ---------------- device scratch (no allocations allowed) ----------------
__device__ float g_h[(size_t)T_TOK * HID];
__device__ float g_norm[(size_t)T_TOK * HID];
__device__ float g_qkv[(size_t)T_TOK * QKV_N];
__device__ float g_ctx[(size_t)T_TOK * HID];
__device__ float g_act[(size_t)T_TOK * INTER];

// =======================================================================
// Common helpers
// =======================================================================
__device__ __forceinline__ uint32_t swz128(uint32_t o) {
    return o ^ ((o >> 3) & 0x70);
}

struct BF2 { uint32_t hi, lo; };
__device__ __forceinline__ BF2 split2(float a, float b) {
    __nv_bfloat16 ah = __float2bfloat16(a);
    __nv_bfloat16 bh = __float2bfloat16(b);
    __nv_bfloat162 hv; hv.x = ah; hv.y = bh;
    __nv_bfloat162 lv;
    lv.x = __float2bfloat16(a - __bfloat162float(ah));
    lv.y = __float2bfloat16(b - __bfloat162float(bh));
    BF2 r;
    r.hi = *(uint32_t*)&hv;
    r.lo = *(uint32_t*)&lv;
    return r;
}

__device__ __forceinline__ float gegelu_pair(float a_in, float lin_in) {
    float a   = fminf(a_in, LIMIT);
    float lin = fminf(fmaxf(lin_in, -LIMIT), LIMIT);
    float sig = 1.0f / (1.0f + __expf(-1.702f * a));
    return a * sig * (lin + 1.0f);
}

// =======================================================================
// Shared SMEM staging: one K-chunk (64 k) of A and B as split-bf16,
// K-major SW128 rows of exactly 128 bytes.
// Stage layout (65536 B):
//   +0      As_hi  [128 m][64 k]  (16 KB)
//   +16384  As_lo
//   +32768  Bs_hi  [128 n][64 k]  (16 KB)   (B transposed during store)
//   +49152  Bs_lo
// =======================================================================
#define STAGE_BYTES 65536
#define GEMM_SMEM_BYTES (1024 + 2 * STAGE_BYTES)

__device__ __forceinline__ void load_chunk(const float* __restrict__ A,
                                           const float* __restrict__ Bm,
                                           char* st,
                                           int bm, int bn, int kt,
                                           int N, int K, int tid) {
    const int r  = tid & 127;     // row (m for A, n for B)
    const int kh = tid >> 7;      // k half: 0 or 1 (32 k each)
    const uint32_t base = (uint32_t)(r * 128 + kh * 64);

    // ---- A: 128-B contiguous gmem read per thread ----
    {
        const float4* src =
            (const float4*)(A + (size_t)(bm * 128 + r) * K + kt * 64 + kh * 32);
        uint32_t hi[16], lo[16];
#pragma unroll
        for (int q = 0; q < 8; q++) {
            float4 f = src[q];
            BF2 p0 = split2(f.x, f.y);
            BF2 p1 = split2(f.z, f.w);
            hi[q * 2] = p0.hi; hi[q * 2 + 1] = p1.hi;
            lo[q * 2] = p0.lo; lo[q * 2 + 1] = p1.lo;
        }
#pragma unroll
        for (int q = 0; q < 4; q++) {
            uint32_t off = swz128(base + q * 16);
            *(uint4*)(st + off) =
                make_uint4(hi[q * 4], hi[q * 4 + 1], hi[q * 4 + 2], hi[q * 4 + 3]);
            *(uint4*)(st + 16384 + off) =
                make_uint4(lo[q * 4], lo[q * 4 + 1], lo[q * 4 + 2], lo[q * 4 + 3]);
        }
    }
    // ---- B: column strip (stride-N loads, warp-coalesced), store transposed ----
    {
        const float* src = Bm + (size_t)(kt * 64 + kh * 32) * N + bn * 128 + r;
        uint32_t hi[16], lo[16];
#pragma unroll
        for (int q = 0; q < 16; q++) {
            float a = src[(size_t)(2 * q) * N];
            float b = src[(size_t)(2 * q + 1) * N];
            BF2 p = split2(a, b);
            hi[q] = p.hi; lo[q] = p.lo;
        }
#pragma unroll
        for (int q = 0; q < 4; q++) {
            uint32_t off = swz128(base + q * 16);
            *(uint4*)(st + 32768 + off) =
                make_uint4(hi[q * 4], hi[q * 4 + 1], hi[q * 4 + 2], hi[q * 4 + 3]);
            *(uint4*)(st + 49152 + off) =
                make_uint4(lo[q * 4], lo[q * 4 + 1], lo[q * 4 + 2], lo[q * 4 + 3]);
        }
    }
}

// =======================================================================
// tcgen05 helpers (guarded: only on arch-specific targets)
// =======================================================================
#if USE_TCG
__device__ __forceinline__ uint32_t smem_u32(const void* p) {
    uint32_t a;
    asm("{ .reg .u64 t; cvta.to.shared.u64 t, %1; cvt.u32.u64 %0, t; }"
        : "=r"(a) : "l"(p));
    return a;
}
#define TCG_ALLOC(smaddr, n) \
    asm volatile("tcgen05.alloc.cta_group::1.sync.aligned.shared::cta.b32 [%0], %1;" \
                 :: "r"(smaddr), "r"((uint32_t)(n)) : "memory")
#define TCG_DEALLOC(tm, n) \
    asm volatile("tcgen05.dealloc.cta_group::1.sync.aligned.b32 %0, %1;" \
                 :: "r"(tm), "r"((uint32_t)(n)))
#define TCG_RELINQ() \
    asm volatile("tcgen05.relinquish_alloc_permit.cta_group::1.sync.aligned;")
#define TCG_COMMIT(mb) \
    asm volatile("tcgen05.commit.cta_group::1.mbarrier::arrive::one.shared::cluster.b64 [%0];" \
                 :: "r"(mb) : "memory")
#define TCG_FENCE_AFTER()  asm volatile("tcgen05.fence::after_thread_sync;" ::: "memory")
#define TCG_WAIT_LD()      asm volatile("tcgen05.wait::ld.sync.aligned;" ::: "memory")
#define FENCE_PROXY_ASYNC() asm volatile("fence.proxy.async.shared::cta;" ::: "memory")
#define MBAR_INIT(mb, cnt) \
    asm volatile("mbarrier.init.shared.b64 [%0], %1;" :: "r"(mb), "r"((uint32_t)(cnt)) : "memory")

__device__ __forceinline__ void mbar_wait(uint32_t mb, uint32_t parity) {
    asm volatile(
        "{\n\t"
        ".reg .pred P1;\n\t"
        "LAB_WAIT_%=:\n\t"
        "mbarrier.try_wait.parity.acquire.cta.shared::cta.b64 P1, [%0], %1, 0x989680;\n\t"
        "@P1 bra.uni LAB_DONE_%=;\n\t"
        "bra.uni LAB_WAIT_%=;\n\t"
        "LAB_DONE_%=:\n\t"
        "}"
        :: "r"(mb), "r"(parity) : "memory");
}

__device__ __forceinline__ void mma_bf16_ss(uint32_t d_tmem, uint64_t a_desc,
                                            uint64_t b_desc, uint32_t idesc,
                                            uint32_t enable) {
    asm volatile(
        "{\n\t"
        ".reg .pred p;\n\t"
        "setp.ne.u32 p, %5, 0;\n\t"
        "tcgen05.mma.cta_group::1.kind::f16 [%0], %1, %2, %3, {%4, %4, %4, %4}, p;\n\t"
        "}"
        :: "r"(d_tmem), "l"(a_desc), "l"(b_desc), "r"(idesc), "r"(0u), "r"(enable)
        : "memory");
}

#define TCG_LD_X32(r, tm) \
    asm volatile( \
        "tcgen05.ld.sync.aligned.32x32b.x32.b32 " \
        "{%0, %1, %2, %3, %4, %5, %6, %7, " \
        " %8, %9, %10, %11, %12, %13, %14, %15, " \
        " %16, %17, %18, %19, %20, %21, %22, %23, " \
        " %24, %25, %26, %27, %28, %29, %30, %31}, [%32];" \
        : "=r"((r)[0]),  "=r"((r)[1]),  "=r"((r)[2]),  "=r"((r)[3]), \
          "=r"((r)[4]),  "=r"((r)[5]),  "=r"((r)[6]),  "=r"((r)[7]), \
          "=r"((r)[8]),  "=r"((r)[9]),  "=r"((r)[10]), "=r"((r)[11]), \
          "=r"((r)[12]), "=r"((r)[13]), "=r"((r)[14]), "=r"((r)[15]), \
          "=r"((r)[16]), "=r"((r)[17]), "=r"((r)[18]), "=r"((r)[19]), \
          "=r"((r)[20]), "=r"((r)[21]), "=r"((r)[22]), "=r"((r)[23]), \
          "=r"((r)[24]), "=r"((r)[25]), "=r"((r)[26]), "=r"((r)[27]), \
          "=r"((r)[28]), "=r"((r)[29]), "=r"((r)[30]), "=r"((r)[31]) \
        : "r"(tm))

// K-major SW128 descriptor (validated constants: LBO=1, SBO=64, version=1)
static __device__ __forceinline__ uint64_t desc_kmajor(uint32_t addr) {
    const uint64_t base = (uint64_t(2) << 61) | (uint64_t(1) << 46) |
                          (uint64_t(64) << 32) | (uint64_t(1) << 16);
    return base | ((uint64_t)(addr >> 4) & 0x3FFF);
}
// idesc: fp32 accum(1<<4), A bf16(1<<7), B bf16(1<<10), N=64 (8<<17), M=128 (8<<24)
#define MMA_IDESC 0x08100490u
#endif  // USE_TCG

// =======================================================================
// mma.sync fallback helper (baseline sm_80+ instruction, legal on sm_103)
// =======================================================================
__device__ __forceinline__ void mma16816(float* c, const uint32_t* a,
                                         const uint32_t* b) {
    asm volatile(
        "mma.sync.aligned.m16n8k16.row.col.f32.bf16.bf16.f32 "
        "{%0,%1,%2,%3}, {%4,%5,%6,%7}, {%8,%9}, {%0,%1,%2,%3};"
        : "+f"(c[0]), "+f"(c[1]), "+f"(c[2]), "+f"(c[3])
        : "r"(a[0]), "r"(a[1]), "r"(a[2]), "r"(a[3]), "r"(b[0]), "r"(b[1]));
}

// =======================================================================
// Split-bf16 GEMM: C = A(MxK) @ B(KxN), CTA tile 128x128, K-chunk 64.
// EPI 0: +bias ; EPI 1: +addsrc ; EPI 2: +bias then gegelu (writes N/2 cols)
// =======================================================================
template <int EPI>
__global__ void __launch_bounds__(256, 1) tc_gemm(const float* __restrict__ A,
                                                  const float* __restrict__ Bm,
                                                  const float* __restrict__ bias,
                                                  const float* __restrict__ addsrc,
                                                  float* __restrict__ C,
                                                  int N, int K, int tiles_n) {
    extern __shared__ __align__(1024) char smem[];
    const int tid  = threadIdx.x;
    const int wid  = tid >> 5;
    const int lane = tid & 31;

    // supertile rasterization: groups of 8 bm rows for L2 reuse
    const int lin = blockIdx.x;
    const int per = 8 * tiles_n;
    const int grp = lin / per, rem = lin % per;
    const int bm = grp * 8 + (rem & 7);
    const int bn = rem >> 3;

    const int KT = K >> 6;

#if USE_TCG
    // ---------------- tcgen05 path ----------------
    const uint32_t sb = smem_u32(smem);
    if (wid == 0) TCG_ALLOC(sb + 0, 128);
    if (tid == 0) { MBAR_INIT(sb + 16, 1); MBAR_INIT(sb + 24, 1); }
    __syncthreads();
    uint32_t tmem;
    asm volatile("ld.shared.b32 %0, [%1];" : "=r"(tmem) : "r"(sb + 0));
    if (wid == 0) TCG_RELINQ();

    load_chunk(A, Bm, smem + 1024, bm, bn, 0, N, K, tid);
    FENCE_PROXY_ASYNC();
    __syncthreads();

    int ph0 = 0, ph1 = 0;
#pragma unroll 1
    for (int kt = 0; kt < KT; kt++) {
        const int cur = kt & 1;
        if (tid == 0) {
            uint32_t so = sb + 1024 + cur * STAGE_BYTES;
            uint64_t dAh  = desc_kmajor(so);
            uint64_t dAl  = desc_kmajor(so + 16384);
            uint64_t dB0h = desc_kmajor(so + 32768);
            uint64_t dB0l = desc_kmajor(so + 49152);
            uint64_t dB1h = desc_kmajor(so + 32768 + 8192);  // n rows 64..127
            uint64_t dB1l = desc_kmajor(so + 49152 + 8192);
#pragma unroll
            for (int ks = 0; ks < 4; ks++) {
                uint32_t en = (kt > 0 || ks > 0) ? 1u : 0u;
                uint64_t o = (uint64_t)(ks * 2);
                mma_bf16_ss(tmem,      dAh + o, dB0h + o, MMA_IDESC, en);
                mma_bf16_ss(tmem,      dAh + o, dB0l + o, MMA_IDESC, 1);
                mma_bf16_ss(tmem,      dAl + o, dB0h + o, MMA_IDESC, 1);
                mma_bf16_ss(tmem + 64, dAh + o, dB1h + o, MMA_IDESC, en);
                mma_bf16_ss(tmem + 64, dAh + o, dB1l + o, MMA_IDESC, 1);
                mma_bf16_ss(tmem + 64, dAl + o, dB1h + o, MMA_IDESC, 1);
            }
            TCG_COMMIT(sb + 16 + cur * 8);
        }
        if (kt + 1 < KT) {
            const int nxt = cur ^ 1;
            if (kt >= 1) {
                if (nxt == 0) { mbar_wait(sb + 16, ph0); ph0 ^= 1; }
                else          { mbar_wait(sb + 24, ph1); ph1 ^= 1; }
            }
            load_chunk(A, Bm, smem + 1024 + nxt * STAGE_BYTES, bm, bn, kt + 1, N, K, tid);
            FENCE_PROXY_ASYNC();
        }
        __syncthreads();
    }
    const int last = (KT - 1) & 1;
    if (last == 0) mbar_wait(sb + 16, ph0);
    else           mbar_wait(sb + 24, ph1);
    TCG_FENCE_AFTER();

    // epilogue from TMEM: warp w -> rows (w&3)*32+lane, cols (w>>2)*64..+64
    const int row = bm * 128 + (wid & 3) * 32 + lane;
#pragma unroll
    for (int cb = 0; cb < 2; cb++) {
        const int c0 = (wid >> 2) * 64 + cb * 32;
        uint32_t r[32];
        TCG_LD_X32(r, tmem + c0);
        TCG_WAIT_LD();
        const int gc0 = bn * 128 + c0;
        if (EPI == 2) {
            float o[16];
#pragma unroll
            for (int t = 0; t < 16; t++) {
                float a   = __uint_as_float(r[2 * t])     + bias[gc0 + 2 * t];
                float lin = __uint_as_float(r[2 * t + 1]) + bias[gc0 + 2 * t + 1];
                o[t] = gegelu_pair(a, lin);
            }
            float* dst = C + (size_t)row * (N >> 1) + (gc0 >> 1);
#pragma unroll
            for (int q = 0; q < 4; q++)
                *(float4*)(dst + q * 4) =
                    make_float4(o[q * 4], o[q * 4 + 1], o[q * 4 + 2], o[q * 4 + 3]);
        } else {
            float o[32];
#pragma unroll
            for (int j = 0; j < 32; j++) o[j] = __uint_as_float(r[j]);
            if (EPI == 0) {
#pragma unroll
                for (int j = 0; j < 32; j++) o[j] += bias[gc0 + j];
            } else {
                const float* ad = addsrc + (size_t)row * N + gc0;
#pragma unroll
                for (int q = 0; q < 8; q++) {
                    float4 av = *(const float4*)(ad + q * 4);
                    o[q * 4 + 0] += av.x; o[q * 4 + 1] += av.y;
                    o[q * 4 + 2] += av.z; o[q * 4 + 3] += av.w;
                }
            }
            float* dst = C + (size_t)row * N + gc0;
#pragma unroll
            for (int q = 0; q < 8; q++)
                *(float4*)(dst + q * 4) =
                    make_float4(o[q * 4], o[q * 4 + 1], o[q * 4 + 2], o[q * 4 + 3]);
        }
    }
    __syncthreads();
    if (wid == 0) TCG_DEALLOC(tmem, 128);

#else
    // ---------------- mma.sync (HMMA) fallback path ----------------
    // 8 warps in 4x2: warp tile m32 x n64.
    const int wm = (wid >> 1) * 32;
    const int wn = (wid & 1) * 64;
    const int gid = lane >> 2, tg = lane & 3;
    char* st = smem + 1024;

    float acc[2][8][4];
#pragma unroll
    for (int mi = 0; mi < 2; mi++)
#pragma unroll
        for (int ni = 0; ni < 8; ni++)
#pragma unroll
            for (int q = 0; q < 4; q++) acc[mi][ni][q] = 0.f;

#pragma unroll 1
    for (int kt = 0; kt < KT; kt++) {
        __syncthreads();
        load_chunk(A, Bm, st, bm, bn, kt, N, K, tid);
        __syncthreads();

#pragma unroll
        for (int ks = 0; ks < 4; ks++) {
            const uint32_t kb = ks * 32;   // byte offset of this k16 within row
            uint32_t ah[2][4], al[2][4];
#pragma unroll
            for (int mi = 0; mi < 2; mi++) {
                uint32_t r0 = (uint32_t)((wm + mi * 16 + gid) * 128);
                uint32_t r1 = r0 + 8 * 128;
                uint32_t o0 = swz128(r0 + kb + tg * 4);
                uint32_t o1 = swz128(r1 + kb + tg * 4);
                uint32_t o2 = swz128(r0 + kb + 16 + tg * 4);
                uint32_t o3 = swz128(r1 + kb + 16 + tg * 4);
                ah[mi][0] = *(uint32_t*)(st + o0);
                ah[mi][1] = *(uint32_t*)(st + o1);
                ah[mi][2] = *(uint32_t*)(st + o2);
                ah[mi][3] = *(uint32_t*)(st + o3);
                al[mi][0] = *(uint32_t*)(st + 16384 + o0);
                al[mi][1] = *(uint32_t*)(st + 16384 + o1);
                al[mi][2] = *(uint32_t*)(st + 16384 + o2);
                al[mi][3] = *(uint32_t*)(st + 16384 + o3);
            }
            uint32_t bh[8][2], bl[8][2];
#pragma unroll
            for (int ni = 0; ni < 8; ni++) {
                uint32_t rn = (uint32_t)((wn + ni * 8 + gid) * 128);
                uint32_t o0 = swz128(rn + kb + tg * 4);
                uint32_t o1 = swz128(rn + kb + 16 + tg * 4);
                bh[ni][0] = *(uint32_t*)(st + 32768 + o0);
                bh[ni][1] = *(uint32_t*)(st + 32768 + o1);
                bl[ni][0] = *(uint32_t*)(st + 49152 + o0);
                bl[ni][1] = *(uint32_t*)(st + 49152 + o1);
            }
#pragma unroll
            for (int mi = 0; mi < 2; mi++)
#pragma unroll
                for (int ni = 0; ni < 8; ni++) {
                    mma16816(acc[mi][ni], ah[mi], bh[ni]);
                    mma16816(acc[mi][ni], ah[mi], bl[ni]);
                    mma16816(acc[mi][ni], al[mi], bh[ni]);
                }
        }
    }

    // epilogue from registers
#pragma unroll
    for (int mi = 0; mi < 2; mi++) {
#pragma unroll
        for (int ni = 0; ni < 8; ni++) {
            int row0 = bm * 128 + wm + mi * 16 + gid;
            int row1 = row0 + 8;
            int col  = bn * 128 + wn + ni * 8 + tg * 2;
            float c0 = acc[mi][ni][0], c1 = acc[mi][ni][1];
            float c2 = acc[mi][ni][2], c3 = acc[mi][ni][3];
            if (EPI == 2) {
                float b0 = bias[col], b1 = bias[col + 1];
                C[(size_t)row0 * (N >> 1) + (col >> 1)] = gegelu_pair(c0 + b0, c1 + b1);
                C[(size_t)row1 * (N >> 1) + (col >> 1)] = gegelu_pair(c2 + b0, c3 + b1);
            } else if (EPI == 0) {
                float b0 = bias[col], b1 = bias[col + 1];
                *(float2*)(C + (size_t)row0 * N + col) = make_float2(c0 + b0, c1 + b1);
                *(float2*)(C + (size_t)row1 * N + col) = make_float2(c2 + b0, c3 + b1);
            } else {
                float2 a0 = *(const float2*)(addsrc + (size_t)row0 * N + col);
                float2 a1 = *(const float2*)(addsrc + (size_t)row1 * N + col);
                *(float2*)(C + (size_t)row0 * N + col) = make_float2(c0 + a0.x, c1 + a0.y);
                *(float2*)(C + (size_t)row1 * N + col) = make_float2(c2 + a1.x, c3 + a1.y);
            }
        }
    }
#endif
}

// =======================================================================
// LayerNorm (optionally fused residual add)
// =======================================================================
__global__ void ln_kernel(const float* __restrict__ x,
                          const float* __restrict__ res,
                          const float* __restrict__ w,
                          const float* __restrict__ b,
                          float* __restrict__ h_out,
                          float* __restrict__ n_out) {
    __shared__ float sred[256];
    const int row = blockIdx.x;
    const int tid = threadIdx.x;
    const size_t base = (size_t)row * HID;

    float vals[16];
    float s = 0.f, s2 = 0.f;
#pragma unroll
    for (int i = 0; i < 16; i++) {
        int c = i * 256 + tid;
        float v = x[base + c];
        if (res)   v += res[base + c];
        if (h_out) h_out[base + c] = v;
        vals[i] = v;
        s += v;
        s2 += v * v;
    }
    sred[tid] = s; __syncthreads();
    for (int off = 128; off > 0; off >>= 1) {
        if (tid < off) sred[tid] += sred[tid + off];
        __syncthreads();
    }
    float mean = sred[0] * (1.0f / HID);
    __syncthreads();
    sred[tid] = s2; __syncthreads();
    for (int off = 128; off > 0; off >>= 1) {
        if (tid < off) sred[tid] += sred[tid + off];
        __syncthreads();
    }
    float var = sred[0] * (1.0f / HID) - mean * mean;
    float rstd = rsqrtf(var + LN_EPS);

#pragma unroll
    for (int i = 0; i < 16; i++) {
        int c = i * 256 + tid;
        n_out[base + c] = (vals[i] - mean) * rstd * w[c] + b[c];
    }
}

// =======================================================================
// RoPE (in-place on q and k parts of qkv)
// =======================================================================
__global__ void rope_kernel(float* __restrict__ qkv,
                            const float* __restrict__ cosp,
                            const float* __restrict__ sinp) {
    const int t = blockIdx.x;
    const float* cr = cosp + (size_t)t * 64;
    const float* sr = sinp + (size_t)t * 64;
    for (int i = threadIdx.x; i < (NH + NKV) * 64; i += 256) {
        int h = i >> 6;
        int d = i & 63;
        size_t base = (size_t)t * QKV_N +
                      (h < NH ? (size_t)h * HD : (size_t)NH * HD + (size_t)(h - NH) * HD);
        float c = cr[d], s = sr[d];
        float x1 = qkv[base + d];
        float x2 = qkv[base + 64 + d];
        qkv[base + d]      = x1 * c - x2 * s;
        qkv[base + 64 + d] = x2 * c + x1 * s;
    }
}

// =======================================================================
// Flash attention (causal, GQA 4:1)
// =======================================================================
__global__ void __launch_bounds__(256) attn_kernel(const float* __restrict__ qkv,
                                                   float* __restrict__ ctx) {
    __shared__ float Qs[8][132];
    __shared__ float Ks[32][132];
    __shared__ float Vs[32][132];

    const int qt = blockIdx.x;
    const int h  = blockIdx.y;
    const int b  = blockIdx.z;
    const int tid  = threadIdx.x;
    const int warp = tid >> 5;
    const int lane = tid & 31;

    const int kvh  = h >> 2;
    const int koff = NH * HD + kvh * HD;
    const int voff = NH * HD + NKV * HD + kvh * HD;

    {
        int r = tid >> 5, c = (tid & 31) * 4;
        const float* src = qkv + (size_t)(b * SEQ + qt * 8 + r) * QKV_N + h * HD + c;
        *(float4*)&Qs[r][c] = *(const float4*)src;
    }

    const int qpos = qt * 8 + warp;
    float m = -1e30f, l = 0.f;
    float ax = 0.f, ay = 0.f, az = 0.f, aw = 0.f;

    const int ntiles = (qt * 8 + 7) / 32 + 1;
    for (int kt = 0; kt < ntiles; kt++) {
        __syncthreads();
#pragma unroll
        for (int i = 0; i < 4; i++) {
            int ch = i * 256 + tid;
            int r = ch >> 5, c = (ch & 31) * 4;
            size_t tk = (size_t)(b * SEQ + kt * 32 + r) * QKV_N;
            *(float4*)&Ks[r][c] = *(const float4*)&qkv[tk + koff + c];
            *(float4*)&Vs[r][c] = *(const float4*)&qkv[tk + voff + c];
        }
        __syncthreads();

        float s = 0.f;
#pragma unroll
        for (int d4 = 0; d4 < 32; d4++) {
            float4 qv = *(const float4*)&Qs[warp][d4 * 4];
            float4 kv = *(const float4*)&Ks[lane][d4 * 4];
            s += qv.x * kv.x + qv.y * kv.y + qv.z * kv.z + qv.w * kv.w;
        }
        s *= ATTN_SCALE;
        int kpos = kt * 32 + lane;
        if (kpos > qpos) s = -1e30f;

        float tmax = s;
#pragma unroll
        for (int off = 16; off > 0; off >>= 1)
            tmax = fmaxf(tmax, __shfl_xor_sync(0xffffffffu, tmax, off));
        float mnew  = fmaxf(m, tmax);
        float scale = __expf(m - mnew);
        float p     = __expf(s - mnew);
        float psum = p;
#pragma unroll
        for (int off = 16; off > 0; off >>= 1)
            psum += __shfl_xor_sync(0xffffffffu, psum, off);
        l = l * scale + psum;
        ax *= scale; ay *= scale; az *= scale; aw *= scale;

#pragma unroll
        for (int j = 0; j < 32; j++) {
            float pj = __shfl_sync(0xffffffffu, p, j);
            float4 v = *(const float4*)&Vs[j][lane * 4];
            ax += pj * v.x; ay += pj * v.y; az += pj * v.z; aw += pj * v.w;
        }
        m = mnew;
    }

    float inv = 1.0f / l;
    size_t ob = (size_t)(b * SEQ + qpos) * HID + h * HD + lane * 4;
    *(float4*)&ctx[ob] = make_float4(ax * inv, ay * inv, az * inv, aw * inv);
}

// =======================================================================
// launcher
// =======================================================================
extern "C" void kernel_launch(void* const* d_in, const int* in_sizes, int n_in,
                              void* d_out, int out_size) {
    const float* hs     = (const float*)d_in[0];
    const float* res    = (const float*)d_in[1];
    const float* cosp   = (const float*)d_in[2];
    const float* sinp   = (const float*)d_in[3];
    const float* w_qkv  = (const float*)d_in[5];
    const float* b_qkv  = (const float*)d_in[6];
    const float* w_o    = (const float*)d_in[7];
    const float* w_ln1  = (const float*)d_in[8];
    const float* b_ln1  = (const float*)d_in[9];
    const float* w_ln2  = (const float*)d_in[10];
    const float* b_ln2  = (const float*)d_in[11];
    const float* w_up   = (const float*)d_in[12];
    const float* b_up   = (const float*)d_in[13];
    const float* w_down = (const float*)d_in[14];
    const float* b_down = (const float*)d_in[15];

    float* out     = (float*)d_out;
    float* mlp_out = out;
    float* h2      = out + (size_t)T_TOK * HID;

    float *p_h, *p_norm, *p_qkv, *p_ctx, *p_act;
    cudaGetSymbolAddress((void**)&p_h,    g_h);
    cudaGetSymbolAddress((void**)&p_norm, g_norm);
    cudaGetSymbolAddress((void**)&p_qkv,  g_qkv);
    cudaGetSymbolAddress((void**)&p_ctx,  g_ctx);
    cudaGetSymbolAddress((void**)&p_act,  g_act);

    cudaFuncSetAttribute(tc_gemm<0>, cudaFuncAttributeMaxDynamicSharedMemorySize, GEMM_SMEM_BYTES);
    cudaFuncSetAttribute(tc_gemm<1>, cudaFuncAttributeMaxDynamicSharedMemorySize, GEMM_SMEM_BYTES);
    cudaFuncSetAttribute(tc_gemm<2>, cudaFuncAttributeMaxDynamicSharedMemorySize, GEMM_SMEM_BYTES);

    const int TM = T_TOK / 128;  // 32

    // 1) h = hs + res ; normed = LN1(h)
    ln_kernel<<<T_TOK, 256>>>(hs, res, w_ln1, b_ln1, p_h, p_norm);

    // 2) qkv = normed @ w_qkv + b_qkv
    tc_gemm<0><<<TM * (QKV_N / 128), 256, GEMM_SMEM_BYTES>>>(
        p_norm, w_qkv, b_qkv, nullptr, p_qkv, QKV_N, HID, QKV_N / 128);

    // 3) RoPE in place on q,k
    rope_kernel<<<T_TOK, 256>>>(p_qkv, cosp, sinp);

    // 4) causal flash attention -> ctx
    attn_kernel<<<dim3(SEQ / 8, NH, BATCH), 256>>>(p_qkv, p_ctx);

    // 5) h2 = ctx @ w_o + h   (written to output)
    tc_gemm<1><<<TM * (HID / 128), 256, GEMM_SMEM_BYTES>>>(
        p_ctx, w_o, nullptr, p_h, h2, HID, HID, HID / 128);

    // 6) normed2 = LN2(h2)
    ln_kernel<<<T_TOK, 256>>>(h2, nullptr, w_ln2, b_ln2, nullptr, p_norm);

    // 7) act = gegelu(normed2 @ w_up + b_up)
    tc_gemm<2><<<TM * (UP_N / 128), 256, GEMM_SMEM_BYTES>>>(
        p_norm, w_up, b_up, nullptr, p_act, UP_N, HID, UP_N / 128);

    // 8) mlp_out = act @ w_down + b_down
    tc_gemm<0><<<TM * (HID / 128), 256, GEMM_SMEM_BYTES>>>(
        p_act, w_down, b_down, nullptr, mlp_out, HID, INTER, HID / 128);
}

// round 9
// speedup vs baseline: 2.8955x; 1.0757x over previous
#include <cuda_runtime.h>
#include <cuda_bf16.h>
#include <math.h>
#include <stdint.h>

// ---------------- problem constants ----------------
#define T_TOK   4096
#define HID     4096
#define NH      32
#define NKV     8
#define HD      128
#define INTER   14336
#define BATCH   4
#define SEQ     1024
#define QKV_N   6144            // (NH + 2*NKV) * HD
#define UP_N    28672           // 2 * INTER
#define LIMIT   20.0f
#define LN_EPS  1e-5f
#define ATTN_SCALE 0.08838834764831845f  // 128^-0.5

// ---------------- device scratch (no allocations allowed) ----------------
__device__ float g_h[(size_t)T_TOK * HID];
__device__ float g_qkv[(size_t)T_TOK * QKV_N];
// split-bf16 activation planes
__device__ __nv_bfloat16 g_normh[(size_t)T_TOK * HID];
__device__ __nv_bfloat16 g_norml[(size_t)T_TOK * HID];
__device__ __nv_bfloat16 g_ctxh[(size_t)T_TOK * HID];
__device__ __nv_bfloat16 g_ctxl[(size_t)T_TOK * HID];
__device__ __nv_bfloat16 g_acth[(size_t)T_TOK * INTER];
__device__ __nv_bfloat16 g_actl[(size_t)T_TOK * INTER];
// split-bf16 TRANSPOSED weight planes: [N][K]
__device__ __nv_bfloat16 g_wqkvh[(size_t)QKV_N * HID];
__device__ __nv_bfloat16 g_wqkvl[(size_t)QKV_N * HID];
__device__ __nv_bfloat16 g_woh[(size_t)HID * HID];
__device__ __nv_bfloat16 g_wol[(size_t)HID * HID];
__device__ __nv_bfloat16 g_wuph[(size_t)UP_N * HID];
__device__ __nv_bfloat16 g_wupl[(size_t)UP_N * HID];
__device__ __nv_bfloat16 g_wdnh[(size_t)HID * INTER];
__device__ __nv_bfloat16 g_wdnl[(size_t)HID * INTER];

// =======================================================================
// Helpers
// =======================================================================
__device__ __forceinline__ uint32_t swz128(uint32_t o) {
    return o ^ ((o >> 3) & 0x70);
}
__device__ __forceinline__ uint32_t smem_u32(const void* p) {
    uint32_t a;
    asm("{ .reg .u64 t; cvta.to.shared.u64 t, %1; cvt.u32.u64 %0, t; }"
        : "=r"(a) : "l"(p));
    return a;
}
__device__ __forceinline__ void cp16(uint32_t s, const void* g) {
    asm volatile("cp.async.cg.shared.global [%0], [%1], 16;" :: "r"(s), "l"(g));
}
#define CP_COMMIT() asm volatile("cp.async.commit_group;" ::: "memory")
#define CP_WAIT2()  asm volatile("cp.async.wait_group 2;" ::: "memory")

__device__ __forceinline__ float gegelu_pair(float a_in, float lin_in) {
    float a   = fminf(a_in, LIMIT);
    float lin = fminf(fmaxf(lin_in, -LIMIT), LIMIT);
    float sig = 1.0f / (1.0f + __expf(-1.702f * a));
    return a * sig * (lin + 1.0f);
}
__device__ __forceinline__ void split1(float v, __nv_bfloat16& h, __nv_bfloat16& l) {
    h = __float2bfloat16(v);
    l = __float2bfloat16(v - __bfloat162float(h));
}
// pack two floats into hi/lo bf16x2 words
__device__ __forceinline__ void split2w(float a, float b, uint32_t& hw, uint32_t& lw) {
    __nv_bfloat162 hv, lv;
    hv.x = __float2bfloat16(a);
    hv.y = __float2bfloat16(b);
    lv.x = __float2bfloat16(a - __bfloat162float(hv.x));
    lv.y = __float2bfloat16(b - __bfloat162float(hv.y));
    hw = *(uint32_t*)&hv;
    lw = *(uint32_t*)&lv;
}

__device__ __forceinline__ void mma16816(float* c, const uint32_t* a,
                                         const uint32_t* b) {
    asm volatile(
        "mma.sync.aligned.m16n8k16.row.col.f32.bf16.bf16.f32 "
        "{%0,%1,%2,%3}, {%4,%5,%6,%7}, {%8,%9}, {%0,%1,%2,%3};"
        : "+f"(c[0]), "+f"(c[1]), "+f"(c[2]), "+f"(c[3])
        : "r"(a[0]), "r"(a[1]), "r"(a[2]), "r"(a[3]), "r"(b[0]), "r"(b[1]));
}

// =======================================================================
// Weight transpose + split: w [K][N] fp32 -> th, tl [N][K] bf16.
// Tile 64k x 32n, block (32, 8). Reads coalesced, writes 128B rows.
// =======================================================================
__global__ void wsplit_kernel(const float* __restrict__ w,
                              __nv_bfloat16* __restrict__ th,
                              __nv_bfloat16* __restrict__ tl,
                              int K, int N) {
    __shared__ float s[64][33];
    const int k0 = blockIdx.y * 64, n0 = blockIdx.x * 32;
    const int tx = threadIdx.x, ty = threadIdx.y;
#pragma unroll
    for (int i = 0; i < 8; i++) {
        int k = ty + i * 8;
        s[k][tx] = w[(size_t)(k0 + k) * N + n0 + tx];
    }
    __syncthreads();
#pragma unroll
    for (int j = 0; j < 4; j++) {
        int n = ty * 4 + j;
        uint32_t hw, lw;
        split2w(s[tx * 2][n], s[tx * 2 + 1][n], hw, lw);
        size_t o = (size_t)(n0 + n) * K + k0 + tx * 2;
        *(uint32_t*)&th[o] = hw;
        *(uint32_t*)&tl[o] = lw;
    }
}

// =======================================================================
// LayerNorm (optionally fused residual add); writes split-bf16 planes
// =======================================================================
__global__ void ln_kernel(const float* __restrict__ x,
                          const float* __restrict__ res,
                          const float* __restrict__ w,
                          const float* __restrict__ b,
                          float* __restrict__ h_out,
                          __nv_bfloat16* __restrict__ nh,
                          __nv_bfloat16* __restrict__ nl) {
    __shared__ float sred[256];
    const int row = blockIdx.x;
    const int tid = threadIdx.x;
    const size_t base = (size_t)row * HID;

    float vals[16];
    float s = 0.f, s2 = 0.f;
#pragma unroll
    for (int i = 0; i < 16; i++) {
        int c = i * 256 + tid;
        float v = x[base + c];
        if (res)   v += res[base + c];
        if (h_out) h_out[base + c] = v;
        vals[i] = v;
        s += v;
        s2 += v * v;
    }
    sred[tid] = s; __syncthreads();
    for (int off = 128; off > 0; off >>= 1) {
        if (tid < off) sred[tid] += sred[tid + off];
        __syncthreads();
    }
    float mean = sred[0] * (1.0f / HID);
    __syncthreads();
    sred[tid] = s2; __syncthreads();
    for (int off = 128; off > 0; off >>= 1) {
        if (tid < off) sred[tid] += sred[tid + off];
        __syncthreads();
    }
    float var = sred[0] * (1.0f / HID) - mean * mean;
    float rstd = rsqrtf(var + LN_EPS);

#pragma unroll
    for (int i = 0; i < 16; i++) {
        int c = i * 256 + tid;
        float v = (vals[i] - mean) * rstd * w[c] + b[c];
        __nv_bfloat16 h, l;
        split1(v, h, l);
        nh[base + c] = h;
        nl[base + c] = l;
    }
}

// =======================================================================
// RoPE (in-place on q and k parts of qkv)
// =======================================================================
__global__ void rope_kernel(float* __restrict__ qkv,
                            const float* __restrict__ cosp,
                            const float* __restrict__ sinp) {
    const int t = blockIdx.x;
    const float* cr = cosp + (size_t)t * 64;
    const float* sr = sinp + (size_t)t * 64;
    for (int i = threadIdx.x; i < (NH + NKV) * 64; i += 256) {
        int h = i >> 6;
        int d = i & 63;
        size_t base = (size_t)t * QKV_N +
                      (h < NH ? (size_t)h * HD : (size_t)NH * HD + (size_t)(h - NH) * HD);
        float c = cr[d], s = sr[d];
        float x1 = qkv[base + d];
        float x2 = qkv[base + 64 + d];
        qkv[base + d]      = x1 * c - x2 * s;
        qkv[base + 64 + d] = x2 * c + x1 * s;
    }
}

// =======================================================================
// Flash attention (causal, GQA). 512 threads = 16 warps.
// Block covers 8 q-rows x 2 q-heads sharing one staged K/V tile stream.
// grid = (SEQ/8, NKV*2, BATCH). Writes ctx as split-bf16 planes.
// =======================================================================
__global__ void __launch_bounds__(512) attn_kernel(const float* __restrict__ qkv,
                                                   __nv_bfloat16* __restrict__ ctxh,
                                                   __nv_bfloat16* __restrict__ ctxl) {
    __shared__ float Qs[16][132];
    __shared__ float Ks[32][132];
    __shared__ float Vs[32][132];

    const int qt  = blockIdx.x;
    const int kvh = blockIdx.y >> 1;
    const int hp  = blockIdx.y & 1;     // head pair within kv group
    const int b   = blockIdx.z;
    const int tid  = threadIdx.x;
    const int warp = tid >> 5;          // 0..15
    const int lane = tid & 31;
    const int qrow = warp & 7;
    const int hloc = warp >> 3;         // 0..1
    const int hq   = kvh * 4 + hp * 2 + hloc;

    const int koff = NH * HD + kvh * HD;
    const int voff = NH * HD + NKV * HD + kvh * HD;

    // load 16 (row, head) Q rows: rh encodes hloc*8 + row (matches warp id)
    {
        int rh = tid >> 5, c = (tid & 31) * 4;
        const float* src = qkv + (size_t)(b * SEQ + qt * 8 + (rh & 7)) * QKV_N +
                           (kvh * 4 + hp * 2 + (rh >> 3)) * HD + c;
        *(float4*)&Qs[rh][c] = *(const float4*)src;
    }

    const int qpos = qt * 8 + qrow;
    float m = -1e30f, l = 0.f;
    float ax = 0.f, ay = 0.f, az = 0.f, aw = 0.f;

    const int ntiles = (qt * 8 + 7) / 32 + 1;
    for (int kt = 0; kt < ntiles; kt++) {
        __syncthreads();
        // stage 32 keys + values with 512 threads: 2 float4 each
#pragma unroll
        for (int i = 0; i < 2; i++) {
            int ch = i * 512 + tid;
            int r = ch >> 5, c = (ch & 31) * 4;
            size_t tk = (size_t)(b * SEQ + kt * 32 + r) * QKV_N;
            *(float4*)&Ks[r][c] = *(const float4*)&qkv[tk + koff + c];
            *(float4*)&Vs[r][c] = *(const float4*)&qkv[tk + voff + c];
        }
        __syncthreads();

        float s = 0.f;
#pragma unroll
        for (int d4 = 0; d4 < 32; d4++) {
            float4 qv = *(const float4*)&Qs[warp][d4 * 4];
            float4 kv = *(const float4*)&Ks[lane][d4 * 4];
            s += qv.x * kv.x + qv.y * kv.y + qv.z * kv.z + qv.w * kv.w;
        }
        s *= ATTN_SCALE;
        int kpos = kt * 32 + lane;
        if (kpos > qpos) s = -1e30f;

        float tmax = s;
#pragma unroll
        for (int off = 16; off > 0; off >>= 1)
            tmax = fmaxf(tmax, __shfl_xor_sync(0xffffffffu, tmax, off));
        float mnew  = fmaxf(m, tmax);
        float scale = __expf(m - mnew);
        float p     = __expf(s - mnew);
        float psum = p;
#pragma unroll
        for (int off = 16; off > 0; off >>= 1)
            psum += __shfl_xor_sync(0xffffffffu, psum, off);
        l = l * scale + psum;
        ax *= scale; ay *= scale; az *= scale; aw *= scale;

#pragma unroll
        for (int j = 0; j < 32; j++) {
            float pj = __shfl_sync(0xffffffffu, p, j);
            float4 v = *(const float4*)&Vs[j][lane * 4];
            ax += pj * v.x; ay += pj * v.y; az += pj * v.z; aw += pj * v.w;
        }
        m = mnew;
    }

    float inv = 1.0f / l;
    size_t ob = (size_t)(b * SEQ + qpos) * HID + hq * HD + lane * 4;
    uint32_t h0, l0, h1, l1;
    split2w(ax * inv, ay * inv, h0, l0);
    split2w(az * inv, aw * inv, h1, l1);
    *(uint2*)&ctxh[ob] = make_uint2(h0, h1);
    *(uint2*)&ctxl[ob] = make_uint2(l0, l1);
}

// =======================================================================
// HMMA split-bf16 GEMM, cp.async 3-stage pipeline.
// A planes [M][K] bf16, B planes [N][K] bf16 (pre-transposed).
// CTA tile 128x128, K-chunk 64, 8 warps (m32 x n64 warp tiles).
// Stage (64KB): Ah@0, Al@16K, Bh@32K, Bl@48K; SW128 rows of 128B.
// EPI 0: C=acc+bias ; EPI 1: C=acc+addsrc ; EPI 2: planes=gegelu(acc+bias)
// =======================================================================
#define PIPE 3
#define STAGE_BYTES 65536
#define GEMM_SMEM_BYTES (PIPE * STAGE_BYTES)

__device__ __forceinline__ void stage_issue(uint32_t st,
                                            const __nv_bfloat16* __restrict__ Ah,
                                            const __nv_bfloat16* __restrict__ Al,
                                            const __nv_bfloat16* __restrict__ Bh,
                                            const __nv_bfloat16* __restrict__ Bl,
                                            int bm, int bn, int kt, int K, int tid) {
#pragma unroll
    for (int q = 0; q < 4; q++) {
        int idx = q * 256 + tid;
        int r = idx >> 3, c = idx & 7;
        uint32_t off = swz128((uint32_t)(r * 128 + c * 16));
        size_t ga = (size_t)(bm * 128 + r) * K + kt * 64 + c * 8;
        size_t gb = (size_t)(bn * 128 + r) * K + kt * 64 + c * 8;
        cp16(st + off,         Ah + ga);
        cp16(st + 16384 + off, Al + ga);
        cp16(st + 32768 + off, Bh + gb);
        cp16(st + 49152 + off, Bl + gb);
    }
}

template <int EPI>
__global__ void __launch_bounds__(256, 1) hgemm(const __nv_bfloat16* __restrict__ Ah,
                                                const __nv_bfloat16* __restrict__ Al,
                                                const __nv_bfloat16* __restrict__ Bh,
                                                const __nv_bfloat16* __restrict__ Bl,
                                                const float* __restrict__ bias,
                                                const float* __restrict__ addsrc,
                                                float* __restrict__ C,
                                                __nv_bfloat16* __restrict__ Ch,
                                                __nv_bfloat16* __restrict__ Cl,
                                                int N, int K, int tiles_n) {
    extern __shared__ __align__(1024) char smem[];
    const uint32_t sb = smem_u32(smem);
    const int tid  = threadIdx.x;
    const int wid  = tid >> 5;
    const int lane = tid & 31;

    // supertile rasterization: groups of 8 bm rows for L2 reuse
    const int lin = blockIdx.x;
    const int per = 8 * tiles_n;
    const int grp = lin / per, rem = lin % per;
    const int bm = grp * 8 + (rem & 7);
    const int bn = rem >> 3;

    const int KT = K >> 6;

    const int wm = (wid >> 1) * 32;
    const int wn = (wid & 1) * 64;
    const int gid = lane >> 2, tg = lane & 3;

    float acc[2][8][4];
#pragma unroll
    for (int mi = 0; mi < 2; mi++)
#pragma unroll
        for (int ni = 0; ni < 8; ni++)
#pragma unroll
            for (int q = 0; q < 4; q++) acc[mi][ni][q] = 0.f;

    // prologue: 2 stages in flight
    stage_issue(sb, Ah, Al, Bh, Bl, bm, bn, 0, K, tid);
    CP_COMMIT();
    stage_issue(sb + STAGE_BYTES, Ah, Al, Bh, Bl, bm, bn, 1, K, tid);
    CP_COMMIT();

#pragma unroll 1
    for (int kt = 0; kt < KT; kt++) {
        __syncthreads();                 // all warps finished stage kt-1
        if (kt + 2 < KT)
            stage_issue(sb + ((kt + 2) % PIPE) * STAGE_BYTES,
                        Ah, Al, Bh, Bl, bm, bn, kt + 2, K, tid);
        CP_COMMIT();                     // one group per iteration (maybe empty)
        CP_WAIT2();                      // stage kt complete
        __syncthreads();

        const char* st = smem + (kt % PIPE) * STAGE_BYTES;
#pragma unroll
        for (int ks = 0; ks < 4; ks++) {
            const uint32_t kb = ks * 32;
            uint32_t ah[2][4], al[2][4];
#pragma unroll
            for (int mi = 0; mi < 2; mi++) {
                uint32_t r0 = (uint32_t)((wm + mi * 16 + gid) * 128);
                uint32_t r1 = r0 + 8 * 128;
                uint32_t o0 = swz128(r0 + kb + tg * 4);
                uint32_t o1 = swz128(r1 + kb + tg * 4);
                uint32_t o2 = swz128(r0 + kb + 16 + tg * 4);
                uint32_t o3 = swz128(r1 + kb + 16 + tg * 4);
                ah[mi][0] = *(const uint32_t*)(st + o0);
                ah[mi][1] = *(const uint32_t*)(st + o1);
                ah[mi][2] = *(const uint32_t*)(st + o2);
                ah[mi][3] = *(const uint32_t*)(st + o3);
                al[mi][0] = *(const uint32_t*)(st + 16384 + o0);
                al[mi][1] = *(const uint32_t*)(st + 16384 + o1);
                al[mi][2] = *(const uint32_t*)(st + 16384 + o2);
                al[mi][3] = *(const uint32_t*)(st + 16384 + o3);
            }
            uint32_t bh[8][2], bl[8][2];
#pragma unroll
            for (int ni = 0; ni < 8; ni++) {
                uint32_t rn = (uint32_t)((wn + ni * 8 + gid) * 128);
                uint32_t o0 = swz128(rn + kb + tg * 4);
                uint32_t o1 = swz128(rn + kb + 16 + tg * 4);
                bh[ni][0] = *(const uint32_t*)(st + 32768 + o0);
                bh[ni][1] = *(const uint32_t*)(st + 32768 + o1);
                bl[ni][0] = *(const uint32_t*)(st + 49152 + o0);
                bl[ni][1] = *(const uint32_t*)(st + 49152 + o1);
            }
#pragma unroll
            for (int mi = 0; mi < 2; mi++)
#pragma unroll
                for (int ni = 0; ni < 8; ni++) {
                    mma16816(acc[mi][ni], ah[mi], bh[ni]);
                    mma16816(acc[mi][ni], ah[mi], bl[ni]);
                    mma16816(acc[mi][ni], al[mi], bh[ni]);
                }
        }
    }

    // epilogue
#pragma unroll
    for (int mi = 0; mi < 2; mi++) {
#pragma unroll
        for (int ni = 0; ni < 8; ni++) {
            int row0 = bm * 128 + wm + mi * 16 + gid;
            int row1 = row0 + 8;
            int col  = bn * 128 + wn + ni * 8 + tg * 2;
            float c0 = acc[mi][ni][0], c1 = acc[mi][ni][1];
            float c2 = acc[mi][ni][2], c3 = acc[mi][ni][3];
            if (EPI == 2) {
                float b0 = bias[col], b1 = bias[col + 1];
                float v0 = gegelu_pair(c0 + b0, c1 + b1);
                float v1 = gegelu_pair(c2 + b0, c3 + b1);
                size_t o0 = (size_t)row0 * (N >> 1) + (col >> 1);
                size_t o1 = (size_t)row1 * (N >> 1) + (col >> 1);
                __nv_bfloat16 h, l;
                split1(v0, h, l); Ch[o0] = h; Cl[o0] = l;
                split1(v1, h, l); Ch[o1] = h; Cl[o1] = l;
            } else if (EPI == 0) {
                float b0 = bias[col], b1 = bias[col + 1];
                *(float2*)(C + (size_t)row0 * N + col) = make_float2(c0 + b0, c1 + b1);
                *(float2*)(C + (size_t)row1 * N + col) = make_float2(c2 + b0, c3 + b1);
            } else {
                float2 a0 = *(const float2*)(addsrc + (size_t)row0 * N + col);
                float2 a1 = *(const float2*)(addsrc + (size_t)row1 * N + col);
                *(float2*)(C + (size_t)row0 * N + col) = make_float2(c0 + a0.x, c1 + a0.y);
                *(float2*)(C + (size_t)row1 * N + col) = make_float2(c2 + a1.x, c3 + a1.y);
            }
        }
    }
}

// =======================================================================
// launcher
// =======================================================================
extern "C" void kernel_launch(void* const* d_in, const int* in_sizes, int n_in,
                              void* d_out, int out_size) {
    const float* hs     = (const float*)d_in[0];
    const float* res    = (const float*)d_in[1];
    const float* cosp   = (const float*)d_in[2];
    const float* sinp   = (const float*)d_in[3];
    const float* w_qkv  = (const float*)d_in[5];
    const float* b_qkv  = (const float*)d_in[6];
    const float* w_o    = (const float*)d_in[7];
    const float* w_ln1  = (const float*)d_in[8];
    const float* b_ln1  = (const float*)d_in[9];
    const float* w_ln2  = (const float*)d_in[10];
    const float* b_ln2  = (const float*)d_in[11];
    const float* w_up   = (const float*)d_in[12];
    const float* b_up   = (const float*)d_in[13];
    const float* w_down = (const float*)d_in[14];
    const float* b_down = (const float*)d_in[15];

    float* out     = (float*)d_out;
    float* mlp_out = out;
    float* h2      = out + (size_t)T_TOK * HID;

    float *p_h, *p_qkv;
    __nv_bfloat16 *p_nh, *p_nl, *p_ch, *p_cl, *p_ah, *p_al;
    __nv_bfloat16 *p_wqh, *p_wql, *p_woh, *p_wol, *p_wuh, *p_wul, *p_wdh, *p_wdl;
    cudaGetSymbolAddress((void**)&p_h,    g_h);
    cudaGetSymbolAddress((void**)&p_qkv,  g_qkv);
    cudaGetSymbolAddress((void**)&p_nh,   g_normh);
    cudaGetSymbolAddress((void**)&p_nl,   g_norml);
    cudaGetSymbolAddress((void**)&p_ch,   g_ctxh);
    cudaGetSymbolAddress((void**)&p_cl,   g_ctxl);
    cudaGetSymbolAddress((void**)&p_ah,   g_acth);
    cudaGetSymbolAddress((void**)&p_al,   g_actl);
    cudaGetSymbolAddress((void**)&p_wqh,  g_wqkvh);
    cudaGetSymbolAddress((void**)&p_wql,  g_wqkvl);
    cudaGetSymbolAddress((void**)&p_woh,  g_woh);
    cudaGetSymbolAddress((void**)&p_wol,  g_wol);
    cudaGetSymbolAddress((void**)&p_wuh,  g_wuph);
    cudaGetSymbolAddress((void**)&p_wul,  g_wupl);
    cudaGetSymbolAddress((void**)&p_wdh,  g_wdnh);
    cudaGetSymbolAddress((void**)&p_wdl,  g_wdnl);

    cudaFuncSetAttribute(hgemm<0>, cudaFuncAttributeMaxDynamicSharedMemorySize, GEMM_SMEM_BYTES);
    cudaFuncSetAttribute(hgemm<1>, cudaFuncAttributeMaxDynamicSharedMemorySize, GEMM_SMEM_BYTES);
    cudaFuncSetAttribute(hgemm<2>, cudaFuncAttributeMaxDynamicSharedMemorySize, GEMM_SMEM_BYTES);

    const int TM = T_TOK / 128;  // 32
    dim3 wblk(32, 8);

    // 0) weight transpose + split (amortized per launch)
    wsplit_kernel<<<dim3(QKV_N / 32, HID / 64), wblk>>>(w_qkv, p_wqh, p_wql, HID, QKV_N);
    wsplit_kernel<<<dim3(HID / 32, HID / 64), wblk>>>(w_o, p_woh, p_wol, HID, HID);
    wsplit_kernel<<<dim3(UP_N / 32, HID / 64), wblk>>>(w_up, p_wuh, p_wul, HID, UP_N);
    wsplit_kernel<<<dim3(HID / 32, INTER / 64), wblk>>>(w_down, p_wdh, p_wdl, INTER, HID);

    // 1) h = hs + res ; norm1 planes = LN1(h)
    ln_kernel<<<T_TOK, 256>>>(hs, res, w_ln1, b_ln1, p_h, p_nh, p_nl);

    // 2) qkv = norm1 @ w_qkv + b_qkv (fp32 out)
    hgemm<0><<<TM * (QKV_N / 128), 256, GEMM_SMEM_BYTES>>>(
        p_nh, p_nl, p_wqh, p_wql, b_qkv, nullptr, p_qkv, nullptr, nullptr,
        QKV_N, HID, QKV_N / 128);

    // 3) RoPE in place
    rope_kernel<<<T_TOK, 256>>>(p_qkv, cosp, sinp);

    // 4) attention -> ctx planes
    attn_kernel<<<dim3(SEQ / 8, NKV * 2, BATCH), 512>>>(p_qkv, p_ch, p_cl);

    // 5) h2 = ctx @ w_o + h (fp32 out to d_out)
    hgemm<1><<<TM * (HID / 128), 256, GEMM_SMEM_BYTES>>>(
        p_ch, p_cl, p_woh, p_wol, nullptr, p_h, h2, nullptr, nullptr,
        HID, HID, HID / 128);

    // 6) norm2 planes = LN2(h2)
    ln_kernel<<<T_TOK, 256>>>(h2, nullptr, w_ln2, b_ln2, nullptr, p_nh, p_nl);

    // 7) act planes = gegelu(norm2 @ w_up + b_up)
    hgemm<2><<<TM * (UP_N / 128), 256, GEMM_SMEM_BYTES>>>(
        p_nh, p_nl, p_wuh, p_wul, b_up, nullptr, nullptr, p_ah, p_al,
        UP_N, HID, UP_N / 128);

    // 8) mlp_out = act @ w_down + b_down (fp32 out to d_out)
    hgemm<0><<<TM * (HID / 128), 256, GEMM_SMEM_BYTES>>>(
        p_ah, p_al, p_wdh, p_wdl, b_down, nullptr, mlp_out, nullptr, nullptr,
        HID, INTER, HID / 128);
}